// round 13
// baseline (speedup 1.0000x reference)
#include <cuda_runtime.h>
#include <cstdint>

// ContactMapGeneration: mean/s_obj + farthest point sampling + gather.
// One cluster (8 CTAs x 512 threads) per batch; points in registers as
// 12 packed f32x2 pairs + 1 scalar tail slot (best-known 3485us layout).
// CHANGE vs best: scan loop has NO argmax select chains — only FMNMX
// min-update + max-accumulate; winning slot recovered post-loop by a
// descending equality pass (first-index exact).

#define CLUSTERSZ 8
#define TPB 512
#define NPAIR 12                 // 24 paired slots
#define TAILSLOT 24              // + 1 scalar tail slot -> 25 slots
#define STRIDE (CLUSTERSZ * TPB) // 4096 threads per batch
#define MAXNP 2048
#define BIGF 1e10f

typedef unsigned long long u64;

// ---------------- packed f32x2 helpers (bitwise == scalar rn) ----------------
static __device__ __forceinline__ u64 pk2(float lo, float hi) {
    u64 r; asm("mov.b64 %0, {%1,%2};" : "=l"(r) : "f"(lo), "f"(hi)); return r;
}
static __device__ __forceinline__ void upk2(u64 v, float& lo, float& hi) {
    asm("mov.b64 {%0,%1}, %2;" : "=f"(lo), "=f"(hi) : "l"(v));
}
static __device__ __forceinline__ u64 add2(u64 a, u64 b) {
    u64 r; asm("add.rn.f32x2 %0, %1, %2;" : "=l"(r) : "l"(a), "l"(b)); return r;
}
static __device__ __forceinline__ u64 mul2(u64 a, u64 b) {
    u64 r; asm("mul.rn.f32x2 %0, %1, %2;" : "=l"(r) : "l"(a), "l"(b)); return r;
}

// ---------------- cluster / DSMEM helpers ----------------
static __device__ __forceinline__ unsigned smem_u32(const void* p) {
    return (unsigned)__cvta_generic_to_shared(p);
}
static __device__ __forceinline__ unsigned my_ctarank() {
    unsigned r; asm("mov.u32 %0, %%cluster_ctarank;" : "=r"(r)); return r;
}
static __device__ __forceinline__ void dsmem_st_u64(unsigned addr, unsigned rank, u64 v) {
    asm volatile(
        "{\n\t.reg .b32 r;\n\t"
        "mapa.shared::cluster.u32 r, %0, %1;\n\t"
        "st.shared::cluster.u64 [r], %2;\n\t}"
        :: "r"(addr), "r"(rank), "l"(v) : "memory");
}
static __device__ __forceinline__ void dsmem_st_f32(unsigned addr, unsigned rank, float v) {
    asm volatile(
        "{\n\t.reg .b32 r;\n\t"
        "mapa.shared::cluster.u32 r, %0, %1;\n\t"
        "st.shared::cluster.f32 [r], %2;\n\t}"
        :: "r"(addr), "r"(rank), "f"(v) : "memory");
}
static __device__ __forceinline__ void mbar_arrive_remote(unsigned addr, unsigned rank) {
    asm volatile(
        "{\n\t.reg .b32 r;\n\t"
        "mapa.shared::cluster.u32 r, %0, %1;\n\t"
        "mbarrier.arrive.release.cluster.shared::cluster.b64 _, [r];\n\t}"
        :: "r"(addr), "r"(rank) : "memory");
}
// plain poll (no suspend hint — hint regressed R4 badly)
static __device__ __forceinline__ void mbar_wait(unsigned addr, unsigned parity) {
    asm volatile(
        "{\n\t.reg .pred P;\n"
        "LW%=:\n\t"
        "mbarrier.try_wait.parity.acquire.cluster.shared::cta.b64 P, [%0], %1;\n\t"
        "@!P bra LW%=;\n\t}"
        :: "r"(addr), "r"(parity) : "memory");
}
#define CLUSTER_SYNC() do { \
    asm volatile("barrier.cluster.arrive.aligned;" ::: "memory"); \
    asm volatile("barrier.cluster.wait.aligned;" ::: "memory"); \
} while (0)

// ------------------------------- kernel -------------------------------
__global__ __launch_bounds__(TPB, 1) __cluster_dims__(CLUSTERSZ, 1, 1)
void fps_contact_kernel(const float* __restrict__ mesh,
                        const float* __restrict__ cmap,
                        const int* __restrict__ initf,
                        float* __restrict__ out,
                        int B, int N, int npoint)
{
    // per-warp winners
    __shared__ u64    sh_wkey[16];
    __shared__ float4 sh_wxyz[16];
    // cluster exchange slots, double-buffered, remotely written
    __shared__ u64    sh_ckey[2][CLUSTERSZ];
    __shared__ u64    sh_cxy[2][CLUSTERSZ];
    __shared__ float  sh_cz[2][CLUSTERSZ];
    // stats scratch
    __shared__ float  sh_wsum[16][3];
    __shared__ float  sh_wmax[16];
    __shared__ u64    sh_sxy[CLUSTERSZ];
    __shared__ float  sh_sz[CLUSTERSZ];
    __shared__ float  sh_smax[CLUSTERSZ];
    // selected indices (rank-0 CTA keeps them)
    __shared__ int    sh_fps[MAXNP];
    __shared__ u64    mbar;

    const unsigned rank = my_ctarank();
    const int b    = blockIdx.x / CLUSTERSZ;
    const int tid  = threadIdx.x;
    const int lane = tid & 31;
    const int wid  = tid >> 5;
    const int t    = (int)rank * TPB + tid;        // 0..4095 within batch
    const unsigned mb_addr = smem_u32(&mbar);

    const float* mb = mesh + (size_t)b * N * 3;
    if (npoint > MAXNP) npoint = MAXNP;

    if (tid == 0) {
        asm volatile("mbarrier.init.shared::cta.b64 [%0], %1;"
                     :: "r"(mb_addr), "r"(CLUSTERSZ) : "memory");
    }

    // ---------------- load points into registers (+ local coord table) -------
    u64   PX[NPAIR], PY[NPAIR], PZ[NPAIR];
    float PDa[NPAIR], PDb[NPAIR];                  // even/odd half min-dists
    float4 lq[TAILSLOT + 1];                       // local mem, winner-indexed only
    float tx3, ty3, tz3, PDt;                      // tail slot
    float sx = 0.f, sy = 0.f, sz = 0.f;

#pragma unroll
    for (int q = 0; q < NPAIR; q++) {
        const int p0 = t + (2 * q) * STRIDE;       // always < N (max 98303)
        const int p1 = t + (2 * q + 1) * STRIDE;
        float x0 = mb[(size_t)p0 * 3 + 0], y0 = mb[(size_t)p0 * 3 + 1], z0 = mb[(size_t)p0 * 3 + 2];
        float x1 = mb[(size_t)p1 * 3 + 0], y1 = mb[(size_t)p1 * 3 + 1], z1 = mb[(size_t)p1 * 3 + 2];
        PX[q] = pk2(x0, x1); PY[q] = pk2(y0, y1); PZ[q] = pk2(z0, z1);
        PDa[q] = BIGF; PDb[q] = BIGF;
        lq[2 * q]     = make_float4(x0, y0, z0, 0.f);
        lq[2 * q + 1] = make_float4(x1, y1, z1, 0.f);
        sx += x0 + x1; sy += y0 + y1; sz += z0 + z1;
    }
    {
        const int pt = t + TAILSLOT * STRIDE;
        const bool v = pt < N;
        tx3 = v ? mb[(size_t)pt * 3 + 0] : 0.f;
        ty3 = v ? mb[(size_t)pt * 3 + 1] : 0.f;
        tz3 = v ? mb[(size_t)pt * 3 + 2] : 0.f;
        PDt = v ? BIGF : 0.0f;
        lq[TAILSLOT] = make_float4(tx3, ty3, tz3, 0.f);
        sx += tx3; sy += ty3; sz += tz3;
    }

    // ---------------- batch mean (centroid) ----------------------------------
#pragma unroll
    for (int off = 16; off; off >>= 1) {
        sx += __shfl_xor_sync(0xffffffffu, sx, off);
        sy += __shfl_xor_sync(0xffffffffu, sy, off);
        sz += __shfl_xor_sync(0xffffffffu, sz, off);
    }
    if (lane == 0) { sh_wsum[wid][0] = sx; sh_wsum[wid][1] = sy; sh_wsum[wid][2] = sz; }
    __syncthreads();
    if (wid == 0) {
        float a = (lane < 16) ? sh_wsum[lane][0] : 0.f;
        float c = (lane < 16) ? sh_wsum[lane][1] : 0.f;
        float d = (lane < 16) ? sh_wsum[lane][2] : 0.f;
#pragma unroll
        for (int off = 8; off; off >>= 1) {
            a += __shfl_xor_sync(0xffffffffu, a, off);
            c += __shfl_xor_sync(0xffffffffu, c, off);
            d += __shfl_xor_sync(0xffffffffu, d, off);
        }
        if (lane < CLUSTERSZ) {
            dsmem_st_u64(smem_u32(&sh_sxy[rank]), lane, pk2(a, c));
            dsmem_st_f32(smem_u32(&sh_sz[rank]),  lane, d);
        }
    }
    CLUSTER_SYNC();   // also publishes mbarrier.init cluster-wide

    float txs = 0.f, tys = 0.f, tzs = 0.f;
#pragma unroll
    for (int r = 0; r < CLUSTERSZ; r++) {
        float a, c; upk2(sh_sxy[r], a, c);
        txs += a; tys += c; tzs += sh_sz[r];
    }
    const float cmx = txs / (float)N, cmy = tys / (float)N, cmz = tzs / (float)N;

    // ---------------- s_obj = sqrt(max ||p - mean||^2) ------------------------
    {
        u64 nmx = pk2(-cmx, -cmx), nmy = pk2(-cmy, -cmy), nmz = pk2(-cmz, -cmz);
        float md = 0.f;
#pragma unroll
        for (int q = 0; q < NPAIR; q++) {
            u64 dx = add2(PX[q], nmx);
            u64 dy = add2(PY[q], nmy);
            u64 dz = add2(PZ[q], nmz);
            u64 ss = add2(add2(mul2(dx, dx), mul2(dy, dy)), mul2(dz, dz));
            float d0, d1; upk2(ss, d0, d1);
            md = fmaxf(md, fmaxf(d0, d1));
        }
        if (t + TAILSLOT * STRIDE < N) {
            float dxs = __fadd_rn(tx3, -cmx);
            float dys = __fadd_rn(ty3, -cmy);
            float dzs = __fadd_rn(tz3, -cmz);
            float ds = __fadd_rn(__fadd_rn(__fmul_rn(dxs, dxs), __fmul_rn(dys, dys)),
                                 __fmul_rn(dzs, dzs));
            md = fmaxf(md, ds);
        }
#pragma unroll
        for (int off = 16; off; off >>= 1)
            md = fmaxf(md, __shfl_xor_sync(0xffffffffu, md, off));
        if (lane == 0) sh_wmax[wid] = md;
        __syncthreads();
        if (wid == 0) {
            float m = (lane < 16) ? sh_wmax[lane] : 0.f;
#pragma unroll
            for (int off = 8; off; off >>= 1)
                m = fmaxf(m, __shfl_xor_sync(0xffffffffu, m, off));
            if (lane < CLUSTERSZ)
                dsmem_st_f32(smem_u32(&sh_smax[rank]), lane, m);
        }
        CLUSTER_SYNC();
    }
    float maxd = 0.f;
#pragma unroll
    for (int r = 0; r < CLUSTERSZ; r++) maxd = fmaxf(maxd, sh_smax[r]);
    const float s_obj = sqrtf(maxd);

    // ---------------- FPS main loop ------------------------------------------
    int f = initf[b];
    u64 ncx, ncy, ncz;                             // packed (-c, -c)
    {
        float icx = mb[(size_t)f * 3 + 0];
        float icy = mb[(size_t)f * 3 + 1];
        float icz = mb[(size_t)f * 3 + 2];
        ncx = pk2(-icx, -icx); ncy = pk2(-icy, -icy); ncz = pk2(-icz, -icz);
    }
    unsigned ph = 0;
    int par = 0;

    for (int i = 0; i < npoint; i++) {
        if (rank == 0 && tid == 0) sh_fps[i] = f;
        if (i + 1 == npoint) break;                // last centroid recorded

        // ---- scan: packed distances + FMNMX min-update + FMNMX max-accum ----
        // (no compares/selects in the loop)
        float m0 = 0.0f, m1 = 0.0f;
#pragma unroll
        for (int q = 0; q < NPAIR; q++) {
            u64 dx = add2(PX[q], ncx);             // x + (-cx) == x - cx (exact)
            u64 dy = add2(PY[q], ncy);
            u64 dz = add2(PZ[q], ncz);
            u64 ss = add2(add2(mul2(dx, dx), mul2(dy, dy)), mul2(dz, dz));
            float d0, d1; upk2(ss, d0, d1);
            float n0 = fminf(PDa[q], d0); PDa[q] = n0;
            float n1 = fminf(PDb[q], d1); PDb[q] = n1;
            m0 = fmaxf(m0, n0);
            m1 = fmaxf(m1, n1);
        }
        {   // tail slot
            float nx, ny, nz, dum;
            upk2(ncx, nx, dum); upk2(ncy, ny, dum); upk2(ncz, nz, dum);
            float dxs = __fadd_rn(tx3, nx);
            float dys = __fadd_rn(ty3, ny);
            float dzs = __fadd_rn(tz3, nz);
            float ds = __fadd_rn(__fadd_rn(__fmul_rn(dxs, dxs), __fmul_rn(dys, dys)),
                                 __fmul_rn(dzs, dzs));
            float nt = fminf(PDt, ds); PDt = nt;
            m0 = fmaxf(m0, nt);
        }
        const float m = fmaxf(m0, m1);

        // ---- post-loop argmax recovery: descending pass -> first (lowest) slot
        int bs = 0;
        if (PDt == m) bs = TAILSLOT;
#pragma unroll
        for (int q = NPAIR - 1; q >= 0; q--) {
            if (PDb[q] == m) bs = 2 * q + 1;
            if (PDa[q] == m) bs = 2 * q;
        }
        // (m == 0 edge: PDa[0] <= m forces PDa[0] == 0 -> bs = 0, always valid)

        const unsigned gidx = (unsigned)t + ((unsigned)bs << 12);
        u64 key = ((u64)__float_as_uint(m) << 32) | (unsigned)(~gidx);

        // ---- warp butterfly: key only (first-index ties via ~idx) ------------
#pragma unroll
        for (int off = 16; off; off >>= 1) {
            u64 ok = __shfl_xor_sync(0xffffffffu, key, off);
            if (ok > key) key = ok;
        }
        const unsigned wg = ~(unsigned)key;        // winning global idx in this warp
        if (lane == (int)(wg & 31u)) {
            sh_wkey[wid] = key;
            sh_wxyz[wid] = lq[wg >> 12];           // slot = gidx / 4096
        }
        __syncthreads();

        // ---- threads 0..7: reduce 16 warp winners, push CTA result to CTA[tid]
        if (tid < CLUSTERSZ) {
            u64 bk = sh_wkey[0]; int j = 0;
#pragma unroll
            for (int w = 1; w < 16; w++) {
                u64 k2 = sh_wkey[w];
                if (k2 > bk) { bk = k2; j = w; }
            }
            float4 p = sh_wxyz[j];
            dsmem_st_u64(smem_u32(&sh_ckey[par][rank]), (unsigned)tid, bk);
            dsmem_st_u64(smem_u32(&sh_cxy[par][rank]),  (unsigned)tid, pk2(p.x, p.y));
            dsmem_st_f32(smem_u32(&sh_cz[par][rank]),   (unsigned)tid, p.z);
            mbar_arrive_remote(mb_addr, (unsigned)tid);
        }

        mbar_wait(mb_addr, ph);
        ph ^= 1;

        // ---- all threads reduce the 8 per-CTA candidates identically --------
        u64 bk = sh_ckey[par][0]; int br = 0;
#pragma unroll
        for (int r = 1; r < CLUSTERSZ; r++) {
            u64 k2 = sh_ckey[par][r];
            if (k2 > bk) { bk = k2; br = r; }
        }
        f = (int)(~(unsigned)bk);
        float bx, by; upk2(sh_cxy[par][br], bx, by);
        float bz = sh_cz[par][br];
        ncx = pk2(-bx, -bx); ncy = pk2(-by, -by); ncz = pk2(-bz, -bz);
        par ^= 1;
    }

    __syncthreads();

    // ---------------- gather + write output (rank-0 CTA per batch) -----------
    if (rank == 0) {
        for (int i = tid; i < npoint; i += TPB) {
            const int idx = sh_fps[i];
            const float x = mb[(size_t)idx * 3 + 0];
            const float y = mb[(size_t)idx * 3 + 1];
            const float z = mb[(size_t)idx * 3 + 2];
            const float c = cmap[(size_t)b * N + idx];
            float4 o = make_float4(c, x / s_obj, y / s_obj, z / s_obj);
            reinterpret_cast<float4*>(out)[(size_t)b * npoint + i] = o;
        }
    }
}

// ------------------------------- launch -------------------------------
extern "C" void kernel_launch(void* const* d_in, const int* in_sizes, int n_in,
                              void* d_out, int out_size) {
    const float* mesh  = (const float*)d_in[0];
    const float* cmap  = (const float*)d_in[1];
    const int*   initf = (const int*)d_in[2];

    const int B = in_sizes[2];
    const int N = in_sizes[0] / (3 * B);
    const int npoint = out_size / (4 * B);   // out = [B, npoint, 4] float32

    dim3 grid(B * CLUSTERSZ);
    dim3 block(TPB);
    fps_contact_kernel<<<grid, block>>>(mesh, cmap, initf, (float*)d_out,
                                        B, N, npoint);
}

// round 15
// speedup vs baseline: 1.5949x; 1.5949x over previous
#include <cuda_runtime.h>
#include <cstdint>

// ContactMapGeneration: mean/s_obj + farthest point sampling + gather.
// One cluster (8 CTAs x 512 threads) per batch; 26 point slots/thread as
// 13 packed f32x2 pairs; R3-best scan (in-loop select chains).
// CHANGE vs best (3485us): in-loop cluster exchange uses the HW cluster
// barrier (barrier.cluster) instead of the hand-rolled DSMEM mbarrier
// poll protocol.

#define CLUSTERSZ 8
#define TPB 512
#define NPAIR 13                 // 26 slots; slot 25 is padding (PD=0)
#define STRIDE (CLUSTERSZ * TPB) // 4096 threads per batch
#define MAXNP 2048
#define BIGF 1e10f

typedef unsigned long long u64;

// ---------------- packed f32x2 helpers (bitwise == scalar rn) ----------------
static __device__ __forceinline__ u64 pk2(float lo, float hi) {
    u64 r; asm("mov.b64 %0, {%1,%2};" : "=l"(r) : "f"(lo), "f"(hi)); return r;
}
static __device__ __forceinline__ void upk2(u64 v, float& lo, float& hi) {
    asm("mov.b64 {%0,%1}, %2;" : "=f"(lo), "=f"(hi) : "l"(v));
}
static __device__ __forceinline__ u64 add2(u64 a, u64 b) {
    u64 r; asm("add.rn.f32x2 %0, %1, %2;" : "=l"(r) : "l"(a), "l"(b)); return r;
}
static __device__ __forceinline__ u64 mul2(u64 a, u64 b) {
    u64 r; asm("mul.rn.f32x2 %0, %1, %2;" : "=l"(r) : "l"(a), "l"(b)); return r;
}

// ---------------- cluster / DSMEM helpers ----------------
static __device__ __forceinline__ unsigned smem_u32(const void* p) {
    return (unsigned)__cvta_generic_to_shared(p);
}
static __device__ __forceinline__ unsigned my_ctarank() {
    unsigned r; asm("mov.u32 %0, %%cluster_ctarank;" : "=r"(r)); return r;
}
static __device__ __forceinline__ void dsmem_st_u64(unsigned addr, unsigned rank, u64 v) {
    asm volatile(
        "{\n\t.reg .b32 r;\n\t"
        "mapa.shared::cluster.u32 r, %0, %1;\n\t"
        "st.shared::cluster.u64 [r], %2;\n\t}"
        :: "r"(addr), "r"(rank), "l"(v) : "memory");
}
static __device__ __forceinline__ void dsmem_st_f32(unsigned addr, unsigned rank, float v) {
    asm volatile(
        "{\n\t.reg .b32 r;\n\t"
        "mapa.shared::cluster.u32 r, %0, %1;\n\t"
        "st.shared::cluster.f32 [r], %2;\n\t}"
        :: "r"(addr), "r"(rank), "f"(v) : "memory");
}
#define CLUSTER_SYNC() do { \
    asm volatile("barrier.cluster.arrive.aligned;" ::: "memory"); \
    asm volatile("barrier.cluster.wait.aligned;" ::: "memory"); \
} while (0)

// ------------------------------- kernel -------------------------------
__global__ __launch_bounds__(TPB, 1) __cluster_dims__(CLUSTERSZ, 1, 1)
void fps_contact_kernel(const float* __restrict__ mesh,
                        const float* __restrict__ cmap,
                        const int* __restrict__ initf,
                        float* __restrict__ out,
                        int B, int N, int npoint)
{
    // per-warp winners
    __shared__ u64    sh_wkey[16];
    __shared__ float4 sh_wxyz[16];
    // cluster exchange slots, double-buffered, remotely written
    __shared__ u64    sh_ckey[2][CLUSTERSZ];
    __shared__ u64    sh_cxy[2][CLUSTERSZ];
    __shared__ float  sh_cz[2][CLUSTERSZ];
    // stats scratch
    __shared__ float  sh_wsum[16][3];
    __shared__ float  sh_wmax[16];
    __shared__ u64    sh_sxy[CLUSTERSZ];
    __shared__ float  sh_sz[CLUSTERSZ];
    __shared__ float  sh_smax[CLUSTERSZ];
    // selected indices (rank-0 CTA keeps them)
    __shared__ int    sh_fps[MAXNP];

    const unsigned rank = my_ctarank();
    const int b    = blockIdx.x / CLUSTERSZ;
    const int tid  = threadIdx.x;
    const int lane = tid & 31;
    const int wid  = tid >> 5;
    const int t    = (int)rank * TPB + tid;        // 0..4095 within batch

    const float* mb = mesh + (size_t)b * N * 3;
    if (npoint > MAXNP) npoint = MAXNP;

    // ---------------- load points into registers (+ local coord table) -------
    u64   PX[NPAIR], PY[NPAIR], PZ[NPAIR];
    float PDa[NPAIR], PDb[NPAIR];                  // even/odd half min-dists
    float4 lq[2 * NPAIR];                          // local mem, winner-indexed only
    float sx = 0.f, sy = 0.f, sz = 0.f;

#pragma unroll
    for (int q = 0; q < NPAIR; q++) {
        const int p0 = t + (2 * q) * STRIDE;
        const int p1 = t + (2 * q + 1) * STRIDE;
        const bool v0 = p0 < N, v1 = p1 < N;       // only pair 12 is ever invalid
        float x0 = 0.f, y0 = 0.f, z0 = 0.f, x1 = 0.f, y1 = 0.f, z1 = 0.f;
        if (v0) { x0 = mb[(size_t)p0 * 3 + 0]; y0 = mb[(size_t)p0 * 3 + 1]; z0 = mb[(size_t)p0 * 3 + 2]; }
        if (v1) { x1 = mb[(size_t)p1 * 3 + 0]; y1 = mb[(size_t)p1 * 3 + 1]; z1 = mb[(size_t)p1 * 3 + 2]; }
        PX[q] = pk2(x0, x1); PY[q] = pk2(y0, y1); PZ[q] = pk2(z0, z1);
        PDa[q] = v0 ? BIGF : 0.0f;
        PDb[q] = v1 ? BIGF : 0.0f;
        lq[2 * q]     = make_float4(x0, y0, z0, 0.f);
        lq[2 * q + 1] = make_float4(x1, y1, z1, 0.f);
        sx += x0 + x1; sy += y0 + y1; sz += z0 + z1;
    }

    // ---------------- batch mean (centroid) ----------------------------------
#pragma unroll
    for (int off = 16; off; off >>= 1) {
        sx += __shfl_xor_sync(0xffffffffu, sx, off);
        sy += __shfl_xor_sync(0xffffffffu, sy, off);
        sz += __shfl_xor_sync(0xffffffffu, sz, off);
    }
    if (lane == 0) { sh_wsum[wid][0] = sx; sh_wsum[wid][1] = sy; sh_wsum[wid][2] = sz; }
    __syncthreads();
    if (wid == 0) {
        float a = (lane < 16) ? sh_wsum[lane][0] : 0.f;
        float c = (lane < 16) ? sh_wsum[lane][1] : 0.f;
        float d = (lane < 16) ? sh_wsum[lane][2] : 0.f;
#pragma unroll
        for (int off = 8; off; off >>= 1) {
            a += __shfl_xor_sync(0xffffffffu, a, off);
            c += __shfl_xor_sync(0xffffffffu, c, off);
            d += __shfl_xor_sync(0xffffffffu, d, off);
        }
        if (lane < CLUSTERSZ) {
            dsmem_st_u64(smem_u32(&sh_sxy[rank]), lane, pk2(a, c));
            dsmem_st_f32(smem_u32(&sh_sz[rank]),  lane, d);
        }
    }
    CLUSTER_SYNC();

    float txs = 0.f, tys = 0.f, tzs = 0.f;
#pragma unroll
    for (int r = 0; r < CLUSTERSZ; r++) {
        float a, c; upk2(sh_sxy[r], a, c);
        txs += a; tys += c; tzs += sh_sz[r];
    }
    const float cmx = txs / (float)N, cmy = tys / (float)N, cmz = tzs / (float)N;

    // ---------------- s_obj = sqrt(max ||p - mean||^2) ------------------------
    {
        u64 nmx = pk2(-cmx, -cmx), nmy = pk2(-cmy, -cmy), nmz = pk2(-cmz, -cmz);
        float md = 0.f;
#pragma unroll
        for (int q = 0; q < NPAIR; q++) {
            u64 dx = add2(PX[q], nmx);
            u64 dy = add2(PY[q], nmy);
            u64 dz = add2(PZ[q], nmz);
            u64 ss = add2(add2(mul2(dx, dx), mul2(dy, dy)), mul2(dz, dz));
            float d0, d1; upk2(ss, d0, d1);
            // exclude pad slots (their PD init is 0)
            if (PDa[q] != 0.0f) md = fmaxf(md, d0);
            if (PDb[q] != 0.0f) md = fmaxf(md, d1);
        }
#pragma unroll
        for (int off = 16; off; off >>= 1)
            md = fmaxf(md, __shfl_xor_sync(0xffffffffu, md, off));
        if (lane == 0) sh_wmax[wid] = md;
        __syncthreads();
        if (wid == 0) {
            float m = (lane < 16) ? sh_wmax[lane] : 0.f;
#pragma unroll
            for (int off = 8; off; off >>= 1)
                m = fmaxf(m, __shfl_xor_sync(0xffffffffu, m, off));
            if (lane < CLUSTERSZ)
                dsmem_st_f32(smem_u32(&sh_smax[rank]), lane, m);
        }
        CLUSTER_SYNC();
    }
    float maxd = 0.f;
#pragma unroll
    for (int r = 0; r < CLUSTERSZ; r++) maxd = fmaxf(maxd, sh_smax[r]);
    const float s_obj = sqrtf(maxd);

    // ---------------- FPS main loop ------------------------------------------
    int f = initf[b];
    u64 ncx, ncy, ncz;                             // packed (-c, -c)
    {
        float icx = mb[(size_t)f * 3 + 0];
        float icy = mb[(size_t)f * 3 + 1];
        float icz = mb[(size_t)f * 3 + 2];
        ncx = pk2(-icx, -icx); ncy = pk2(-icy, -icy); ncz = pk2(-icz, -icz);
    }
    int par = 0;

    for (int i = 0; i < npoint; i++) {
        if (rank == 0 && tid == 0) sh_fps[i] = f;
        if (i + 1 == npoint) break;                // last centroid recorded

        // ---- scan (R3-best): min-update + two in-loop argmax chains ---------
        float best0 = -1.0f, best1 = -1.0f;
        int   bs0 = 0, bs1 = 1;
#pragma unroll
        for (int q = 0; q < NPAIR; q++) {
            u64 dx = add2(PX[q], ncx);             // x + (-cx) == x - cx (exact)
            u64 dy = add2(PY[q], ncy);
            u64 dz = add2(PZ[q], ncz);
            u64 ss = add2(add2(mul2(dx, dx), mul2(dy, dy)), mul2(dz, dz));
            float d0, d1; upk2(ss, d0, d1);
            float n0 = fminf(PDa[q], d0); PDa[q] = n0;
            if (n0 > best0) { best0 = n0; bs0 = 2 * q; }
            float n1 = fminf(PDb[q], d1); PDb[q] = n1;
            if (n1 > best1) { best1 = n1; bs1 = 2 * q + 1; }
        }
        // merge chains with exact first-index tie-break
        float best; int bs;
        if (best1 > best0 || (best1 == best0 && bs1 < bs0)) { best = best1; bs = bs1; }
        else                                                { best = best0; bs = bs0; }

        const unsigned gidx = (unsigned)t + ((unsigned)bs << 12);
        u64 key = ((u64)__float_as_uint(best) << 32) | (unsigned)(~gidx);

        // ---- warp butterfly: key only ---------------------------------------
#pragma unroll
        for (int off = 16; off; off >>= 1) {
            u64 ok = __shfl_xor_sync(0xffffffffu, key, off);
            if (ok > key) key = ok;
        }
        const unsigned wg = ~(unsigned)key;        // winning global idx in this warp
        if (lane == (int)(wg & 31u)) {
            sh_wkey[wid] = key;
            sh_wxyz[wid] = lq[wg >> 12];           // slot = gidx / 4096
        }
        __syncthreads();

        // ---- threads 0..7: reduce 16 warp winners, push CTA result to CTA[tid]
        if (tid < CLUSTERSZ) {
            u64 bk = sh_wkey[0]; int j = 0;
#pragma unroll
            for (int w = 1; w < 16; w++) {
                u64 k2 = sh_wkey[w];
                if (k2 > bk) { bk = k2; j = w; }
            }
            float4 p = sh_wxyz[j];
            dsmem_st_u64(smem_u32(&sh_ckey[par][rank]), (unsigned)tid, bk);
            dsmem_st_u64(smem_u32(&sh_cxy[par][rank]),  (unsigned)tid, pk2(p.x, p.y));
            dsmem_st_f32(smem_u32(&sh_cz[par][rank]),   (unsigned)tid, p.z);
        }

        // ---- HW cluster barrier: orders remote stores, releases all CTAs ----
        CLUSTER_SYNC();

        // ---- all threads reduce the 8 per-CTA candidates identically --------
        u64 bk = sh_ckey[par][0]; int br = 0;
#pragma unroll
        for (int r = 1; r < CLUSTERSZ; r++) {
            u64 k2 = sh_ckey[par][r];
            if (k2 > bk) { bk = k2; br = r; }
        }
        f = (int)(~(unsigned)bk);
        float bx, by; upk2(sh_cxy[par][br], bx, by);
        float bz = sh_cz[par][br];
        ncx = pk2(-bx, -bx); ncy = pk2(-by, -by); ncz = pk2(-bz, -bz);
        par ^= 1;
    }

    __syncthreads();

    // ---------------- gather + write output (rank-0 CTA per batch) -----------
    if (rank == 0) {
        for (int i = tid; i < npoint; i += TPB) {
            const int idx = sh_fps[i];
            const float x = mb[(size_t)idx * 3 + 0];
            const float y = mb[(size_t)idx * 3 + 1];
            const float z = mb[(size_t)idx * 3 + 2];
            const float c = cmap[(size_t)b * N + idx];
            float4 o = make_float4(c, x / s_obj, y / s_obj, z / s_obj);
            reinterpret_cast<float4*>(out)[(size_t)b * npoint + i] = o;
        }
    }
}

// ------------------------------- launch -------------------------------
extern "C" void kernel_launch(void* const* d_in, const int* in_sizes, int n_in,
                              void* d_out, int out_size) {
    const float* mesh  = (const float*)d_in[0];
    const float* cmap  = (const float*)d_in[1];
    const int*   initf = (const int*)d_in[2];

    const int B = in_sizes[2];
    const int N = in_sizes[0] / (3 * B);
    const int npoint = out_size / (4 * B);   // out = [B, npoint, 4] float32

    dim3 grid(B * CLUSTERSZ);
    dim3 block(TPB);
    fps_contact_kernel<<<grid, block>>>(mesh, cmap, initf, (float*)d_out,
                                        B, N, npoint);
}

// round 16
// speedup vs baseline: 1.6870x; 1.0577x over previous
#include <cuda_runtime.h>
#include <cstdint>

// ContactMapGeneration: mean/s_obj + farthest point sampling + gather.
// One cluster (8 CTAs x 512 threads) per batch; 26 point slots/thread as
// 13 packed f32x2 pairs; R3 scan with in-loop argmax chains.
// R16: key-only reduction tail (REDUX warp reduce; no coordinate payload,
// no local coord table) — winner coords re-fetched via uniform __ldg
// (L2 broadcast) after the cluster barrier. Cuts register pressure.

#define CLUSTERSZ 8
#define TPB 512
#define NPAIR 13                 // 26 slots; slot 25 is padding (PD=0)
#define STRIDE (CLUSTERSZ * TPB) // 4096 threads per batch
#define MAXNP 2048
#define BIGF 1e10f

typedef unsigned long long u64;

// ---------------- packed f32x2 helpers (bitwise == scalar rn) ----------------
static __device__ __forceinline__ u64 pk2(float lo, float hi) {
    u64 r; asm("mov.b64 %0, {%1,%2};" : "=l"(r) : "f"(lo), "f"(hi)); return r;
}
static __device__ __forceinline__ void upk2(u64 v, float& lo, float& hi) {
    asm("mov.b64 {%0,%1}, %2;" : "=f"(lo), "=f"(hi) : "l"(v));
}
static __device__ __forceinline__ u64 add2(u64 a, u64 b) {
    u64 r; asm("add.rn.f32x2 %0, %1, %2;" : "=l"(r) : "l"(a), "l"(b)); return r;
}
static __device__ __forceinline__ u64 mul2(u64 a, u64 b) {
    u64 r; asm("mul.rn.f32x2 %0, %1, %2;" : "=l"(r) : "l"(a), "l"(b)); return r;
}

// ---------------- cluster / DSMEM helpers ----------------
static __device__ __forceinline__ unsigned smem_u32(const void* p) {
    return (unsigned)__cvta_generic_to_shared(p);
}
static __device__ __forceinline__ unsigned my_ctarank() {
    unsigned r; asm("mov.u32 %0, %%cluster_ctarank;" : "=r"(r)); return r;
}
static __device__ __forceinline__ void dsmem_st_u64(unsigned addr, unsigned rank, u64 v) {
    asm volatile(
        "{\n\t.reg .b32 r;\n\t"
        "mapa.shared::cluster.u32 r, %0, %1;\n\t"
        "st.shared::cluster.u64 [r], %2;\n\t}"
        :: "r"(addr), "r"(rank), "l"(v) : "memory");
}
static __device__ __forceinline__ void dsmem_st_f32(unsigned addr, unsigned rank, float v) {
    asm volatile(
        "{\n\t.reg .b32 r;\n\t"
        "mapa.shared::cluster.u32 r, %0, %1;\n\t"
        "st.shared::cluster.f32 [r], %2;\n\t}"
        :: "r"(addr), "r"(rank), "f"(v) : "memory");
}
#define CLUSTER_SYNC() do { \
    asm volatile("barrier.cluster.arrive.aligned;" ::: "memory"); \
    asm volatile("barrier.cluster.wait.aligned;" ::: "memory"); \
} while (0)

// ------------------------------- kernel -------------------------------
__global__ __launch_bounds__(TPB, 1) __cluster_dims__(CLUSTERSZ, 1, 1)
void fps_contact_kernel(const float* __restrict__ mesh,
                        const float* __restrict__ cmap,
                        const int* __restrict__ initf,
                        float* __restrict__ out,
                        int B, int N, int npoint)
{
    // per-warp winners (keys only)
    __shared__ u64    sh_wkey[16];
    // cluster exchange slots, double-buffered, remotely written (keys only)
    __shared__ u64    sh_ckey[2][CLUSTERSZ];
    // stats scratch
    __shared__ float  sh_wsum[16][3];
    __shared__ float  sh_wmax[16];
    __shared__ u64    sh_sxy[CLUSTERSZ];
    __shared__ float  sh_sz[CLUSTERSZ];
    __shared__ float  sh_smax[CLUSTERSZ];
    // selected indices (rank-0 CTA keeps them)
    __shared__ int    sh_fps[MAXNP];

    const unsigned rank = my_ctarank();
    const int b    = blockIdx.x / CLUSTERSZ;
    const int tid  = threadIdx.x;
    const int lane = tid & 31;
    const int wid  = tid >> 5;
    const int t    = (int)rank * TPB + tid;        // 0..4095 within batch

    const float* mb = mesh + (size_t)b * N * 3;
    if (npoint > MAXNP) npoint = MAXNP;

    // ---------------- load points into registers ------------------------------
    u64   PX[NPAIR], PY[NPAIR], PZ[NPAIR];
    float PDa[NPAIR], PDb[NPAIR];                  // even/odd half min-dists
    float sx = 0.f, sy = 0.f, sz = 0.f;

#pragma unroll
    for (int q = 0; q < NPAIR; q++) {
        const int p0 = t + (2 * q) * STRIDE;
        const int p1 = t + (2 * q + 1) * STRIDE;
        const bool v0 = p0 < N, v1 = p1 < N;       // only pair 12 is ever invalid
        float x0 = 0.f, y0 = 0.f, z0 = 0.f, x1 = 0.f, y1 = 0.f, z1 = 0.f;
        if (v0) { x0 = mb[(size_t)p0 * 3 + 0]; y0 = mb[(size_t)p0 * 3 + 1]; z0 = mb[(size_t)p0 * 3 + 2]; }
        if (v1) { x1 = mb[(size_t)p1 * 3 + 0]; y1 = mb[(size_t)p1 * 3 + 1]; z1 = mb[(size_t)p1 * 3 + 2]; }
        PX[q] = pk2(x0, x1); PY[q] = pk2(y0, y1); PZ[q] = pk2(z0, z1);
        PDa[q] = v0 ? BIGF : 0.0f;
        PDb[q] = v1 ? BIGF : 0.0f;
        sx += x0 + x1; sy += y0 + y1; sz += z0 + z1;
    }

    // ---------------- batch mean (centroid) ----------------------------------
#pragma unroll
    for (int off = 16; off; off >>= 1) {
        sx += __shfl_xor_sync(0xffffffffu, sx, off);
        sy += __shfl_xor_sync(0xffffffffu, sy, off);
        sz += __shfl_xor_sync(0xffffffffu, sz, off);
    }
    if (lane == 0) { sh_wsum[wid][0] = sx; sh_wsum[wid][1] = sy; sh_wsum[wid][2] = sz; }
    __syncthreads();
    if (wid == 0) {
        float a = (lane < 16) ? sh_wsum[lane][0] : 0.f;
        float c = (lane < 16) ? sh_wsum[lane][1] : 0.f;
        float d = (lane < 16) ? sh_wsum[lane][2] : 0.f;
#pragma unroll
        for (int off = 8; off; off >>= 1) {
            a += __shfl_xor_sync(0xffffffffu, a, off);
            c += __shfl_xor_sync(0xffffffffu, c, off);
            d += __shfl_xor_sync(0xffffffffu, d, off);
        }
        if (lane < CLUSTERSZ) {
            dsmem_st_u64(smem_u32(&sh_sxy[rank]), lane, pk2(a, c));
            dsmem_st_f32(smem_u32(&sh_sz[rank]),  lane, d);
        }
    }
    CLUSTER_SYNC();

    float txs = 0.f, tys = 0.f, tzs = 0.f;
#pragma unroll
    for (int r = 0; r < CLUSTERSZ; r++) {
        float a, c; upk2(sh_sxy[r], a, c);
        txs += a; tys += c; tzs += sh_sz[r];
    }
    const float cmx = txs / (float)N, cmy = tys / (float)N, cmz = tzs / (float)N;

    // ---------------- s_obj = sqrt(max ||p - mean||^2) ------------------------
    {
        u64 nmx = pk2(-cmx, -cmx), nmy = pk2(-cmy, -cmy), nmz = pk2(-cmz, -cmz);
        float md = 0.f;
#pragma unroll
        for (int q = 0; q < NPAIR; q++) {
            u64 dx = add2(PX[q], nmx);
            u64 dy = add2(PY[q], nmy);
            u64 dz = add2(PZ[q], nmz);
            u64 ss = add2(add2(mul2(dx, dx), mul2(dy, dy)), mul2(dz, dz));
            float d0, d1; upk2(ss, d0, d1);
            // exclude pad slots (their PD init is 0)
            if (PDa[q] != 0.0f) md = fmaxf(md, d0);
            if (PDb[q] != 0.0f) md = fmaxf(md, d1);
        }
#pragma unroll
        for (int off = 16; off; off >>= 1)
            md = fmaxf(md, __shfl_xor_sync(0xffffffffu, md, off));
        if (lane == 0) sh_wmax[wid] = md;
        __syncthreads();
        if (wid == 0) {
            float m = (lane < 16) ? sh_wmax[lane] : 0.f;
#pragma unroll
            for (int off = 8; off; off >>= 1)
                m = fmaxf(m, __shfl_xor_sync(0xffffffffu, m, off));
            if (lane < CLUSTERSZ)
                dsmem_st_f32(smem_u32(&sh_smax[rank]), lane, m);
        }
        CLUSTER_SYNC();
    }
    float maxd = 0.f;
#pragma unroll
    for (int r = 0; r < CLUSTERSZ; r++) maxd = fmaxf(maxd, sh_smax[r]);
    const float s_obj = sqrtf(maxd);

    // ---------------- FPS main loop ------------------------------------------
    int f = initf[b];
    u64 ncx, ncy, ncz;                             // packed (-c, -c)
    {
        float icx = __ldg(mb + (size_t)f * 3 + 0);
        float icy = __ldg(mb + (size_t)f * 3 + 1);
        float icz = __ldg(mb + (size_t)f * 3 + 2);
        ncx = pk2(-icx, -icx); ncy = pk2(-icy, -icy); ncz = pk2(-icz, -icz);
    }
    int par = 0;

    for (int i = 0; i < npoint; i++) {
        if (rank == 0 && tid == 0) sh_fps[i] = f;
        if (i + 1 == npoint) break;                // last centroid recorded

        // ---- scan: min-update + two in-loop argmax chains -------------------
        float best0 = -1.0f, best1 = -1.0f;
        int   bs0 = 0, bs1 = 1;
#pragma unroll
        for (int q = 0; q < NPAIR; q++) {
            u64 dx = add2(PX[q], ncx);             // x + (-cx) == x - cx (exact)
            u64 dy = add2(PY[q], ncy);
            u64 dz = add2(PZ[q], ncz);
            u64 ss = add2(add2(mul2(dx, dx), mul2(dy, dy)), mul2(dz, dz));
            float d0, d1; upk2(ss, d0, d1);
            float n0 = fminf(PDa[q], d0); PDa[q] = n0;
            if (n0 > best0) { best0 = n0; bs0 = 2 * q; }
            float n1 = fminf(PDb[q], d1); PDb[q] = n1;
            if (n1 > best1) { best1 = n1; bs1 = 2 * q + 1; }
        }
        // merge chains with exact first-index tie-break
        float best; int bs;
        if (best1 > best0 || (best1 == best0 && bs1 < bs0)) { best = best1; bs = bs1; }
        else                                                { best = best0; bs = bs0; }

        // ---- warp reduce via REDUX: max dist bits, then min index -----------
        const unsigned bits = __float_as_uint(best);       // best >= 0
        const unsigned wmax = __reduce_max_sync(0xffffffffu, bits);
        const unsigned gidx = (unsigned)t + ((unsigned)bs << 12);  // true point idx
        const unsigned cand = (bits == wmax) ? gidx : 0xffffffffu;
        const unsigned wmin = __reduce_min_sync(0xffffffffu, cand);
        if (cand == wmin) {                                // unique winner lane
            sh_wkey[wid] = ((u64)wmax << 32) | (unsigned)(~wmin);
        }
        __syncthreads();

        // ---- threads 0..7: reduce 16 warp keys, push CTA key to CTA[tid] ----
        if (tid < CLUSTERSZ) {
            u64 bk = sh_wkey[0];
#pragma unroll
            for (int w = 1; w < 16; w++) {
                u64 k2 = sh_wkey[w];
                if (k2 > bk) bk = k2;
            }
            dsmem_st_u64(smem_u32(&sh_ckey[par][rank]), (unsigned)tid, bk);
        }

        // ---- HW cluster barrier: orders remote stores, releases all CTAs ----
        CLUSTER_SYNC();

        // ---- all threads reduce the 8 per-CTA keys identically --------------
        u64 bk = sh_ckey[par][0];
#pragma unroll
        for (int r = 1; r < CLUSTERSZ; r++) {
            u64 k2 = sh_ckey[par][r];
            if (k2 > bk) bk = k2;
        }
        f = (int)(~(unsigned)bk);

        // ---- fetch winner coords: uniform address -> one L2 sector/warp -----
        {
            float bx = __ldg(mb + (size_t)f * 3 + 0);
            float by = __ldg(mb + (size_t)f * 3 + 1);
            float bz = __ldg(mb + (size_t)f * 3 + 2);
            ncx = pk2(-bx, -bx); ncy = pk2(-by, -by); ncz = pk2(-bz, -bz);
        }
        par ^= 1;
    }

    __syncthreads();

    // ---------------- gather + write output (rank-0 CTA per batch) -----------
    if (rank == 0) {
        for (int i = tid; i < npoint; i += TPB) {
            const int idx = sh_fps[i];
            const float x = mb[(size_t)idx * 3 + 0];
            const float y = mb[(size_t)idx * 3 + 1];
            const float z = mb[(size_t)idx * 3 + 2];
            const float c = cmap[(size_t)b * N + idx];
            float4 o = make_float4(c, x / s_obj, y / s_obj, z / s_obj);
            reinterpret_cast<float4*>(out)[(size_t)b * npoint + i] = o;
        }
    }
}

// ------------------------------- launch -------------------------------
extern "C" void kernel_launch(void* const* d_in, const int* in_sizes, int n_in,
                              void* d_out, int out_size) {
    const float* mesh  = (const float*)d_in[0];
    const float* cmap  = (const float*)d_in[1];
    const int*   initf = (const int*)d_in[2];

    const int B = in_sizes[2];
    const int N = in_sizes[0] / (3 * B);
    const int npoint = out_size / (4 * B);   // out = [B, npoint, 4] float32

    dim3 grid(B * CLUSTERSZ);
    dim3 block(TPB);
    fps_contact_kernel<<<grid, block>>>(mesh, cmap, initf, (float*)d_out,
                                        B, N, npoint);
}